// round 3
// baseline (speedup 1.0000x reference)
#include <cuda_runtime.h>

// ---------------------------------------------------------------------------
// Net_17188459119113 — R3
// 4-bit quant conv(1->16,3x3) + bias + relu + maxpool(4) + 4-bit quant FC.
// B=8192. Integer-code dp4a math (exact), scales at the end.
//
// 3 kernels, no global atomics, no init kernel:
//   k_amax : blocks 0..1183 scan x -> g_xpart[]; block 1184 quantizes+packs
//            both weight tensors (writes scales + packs + g_xpart[1184]=0)
//   k_conv : preamble reduces g_xpart -> s_x; fused conv+pool; flat stored
//            float in (b, j, c) layout via 4x STG.128; per-block flat max
//            -> g_fpart[]
//   k_fc   : preamble reduces g_fpart -> s_f; 2 rows/warp dp4a GEMV
// ---------------------------------------------------------------------------

#define BATCH     8192
#define IN_HW     28
#define IN_PIX    784
#define FLAT_DIM  576
#define FC_GROUPS 144
#define XBLOCKS   1184
#define CONVBLOCKS 1152            // 8192*36 / 256
#define FCBLOCKS  512              // 8192 / 16

__device__ float        g_flat[BATCH * FLAT_DIM];     // (b, j, c) layout
__device__ unsigned int g_xpart[XBLOCKS + 1];         // per-block amax(|x|) bits
__device__ unsigned int g_fpart[CONVBLOCKS];          // per-block amax(flat) bits
__device__ int          g_convw_pack[48];             // [c][row] bytes [w0,w1,w2,0]
__device__ int          g_fcw_pack[10 * FC_GROUPS];   // permuted (j,c) packing
__device__ float        g_sw_conv;
__device__ float        g_sw_fc;

__device__ __forceinline__ int qcode(float v, float inv_s) {
    return __float2int_rn(fminf(fmaxf(v * inv_s, -7.0f), 7.0f));
}
__device__ __forceinline__ unsigned pack4(int a, int b, int c, int d) {
    return (unsigned)((a & 0xff) | ((b & 0xff) << 8) | ((c & 0xff) << 16) | (d << 24));
}

// block-wide max of per-thread unsigned, result broadcast to all threads
__device__ __forceinline__ unsigned block_umax(unsigned m, unsigned* sm) {
    if (threadIdx.x == 0) *sm = 0u;
    __syncthreads();
    m = __reduce_max_sync(0xFFFFFFFFu, m);
    if ((threadIdx.x & 31) == 0) atomicMax(sm, m);   // smem atomic only
    __syncthreads();
    return *sm;
}

// ---------------------------------------------------------------------------
// k_amax: x abs-max partials + weight quantization (block XBLOCKS)
// ---------------------------------------------------------------------------
__global__ void __launch_bounds__(256)
k_amax(const float4* __restrict__ x4, int n4,
       const float* __restrict__ conv_w, const float* __restrict__ fc_w) {
    __shared__ unsigned sm;

    if (blockIdx.x == XBLOCKS) {
        // ---- weight quantization block ----
        unsigned m = 0u;
        for (int i = threadIdx.x; i < 144; i += 256)
            m = max(m, __float_as_uint(fabsf(conv_w[i])));
        unsigned cw_bits = block_umax(m, &sm);
        __syncthreads();
        m = 0u;
        for (int i = threadIdx.x; i < 5760; i += 256)
            m = max(m, __float_as_uint(fabsf(fc_w[i])));
        unsigned fw_bits = block_umax(m, &sm);

        float s_cw = __uint_as_float(cw_bits) / 7.0f + 1e-8f;
        float s_fw = __uint_as_float(fw_bits) / 7.0f + 1e-8f;
        if (threadIdx.x == 0) {
            g_sw_conv = s_cw;
            g_sw_fc   = s_fw;
            g_xpart[XBLOCKS] = 0u;
        }
        float inv_cw = 1.0f / s_cw;
        float inv_fw = 1.0f / s_fw;

        // conv: [16][3][3] -> 48 packs
        for (int i = threadIdx.x; i < 48; i += 256) {
            const float* wr = conv_w + i * 3;
            g_fcw_pack[0] = g_fcw_pack[0];  // no-op to keep compiler honest
            g_convw_pack[i] = (int)pack4(qcode(wr[0], inv_cw),
                                         qcode(wr[1], inv_cw),
                                         qcode(wr[2], inv_cw), 0);
        }
        // fc: permuted so group g covers new-k = 4g..4g+3, new-k = j*16+c,
        // original index = c*36 + j
        for (int i = threadIdx.x; i < 10 * FC_GROUPS; i += 256) {
            int o = i / FC_GROUPS, g = i % FC_GROUPS;
            int b4[4];
            #pragma unroll
            for (int t = 0; t < 4; t++) {
                int nk = 4 * g + t;
                int j = nk >> 4, c = nk & 15;
                b4[t] = qcode(fc_w[o * FLAT_DIM + c * 36 + j], inv_fw);
            }
            g_fcw_pack[i] = (int)pack4(b4[0], b4[1], b4[2], b4[3]);
        }
        return;
    }

    // ---- x scan blocks ----
    unsigned m = 0u;
    for (int i = blockIdx.x * 256 + threadIdx.x; i < n4; i += XBLOCKS * 256) {
        float4 v = x4[i];
        m = max(m, __float_as_uint(fabsf(v.x)));
        m = max(m, __float_as_uint(fabsf(v.y)));
        m = max(m, __float_as_uint(fabsf(v.z)));
        m = max(m, __float_as_uint(fabsf(v.w)));
    }
    m = block_umax(m, &sm);
    if (threadIdx.x == 0) g_xpart[blockIdx.x] = m;
}

// ---------------------------------------------------------------------------
// k_conv: thread per (b, ph, pw). dp4a row-products + IADD3 combine,
// int max-pool, scale+bias+relu, 4x STG.128 in (j,c) layout.
// ---------------------------------------------------------------------------
__global__ void __launch_bounds__(256)
k_conv(const float* __restrict__ x, const float* __restrict__ conv_b) {
    __shared__ int      swp[48];
    __shared__ float    sb[16];
    __shared__ unsigned sm;

    // reduce x amax partials (all 1185 slots; slot XBLOCKS is 0)
    unsigned m = 0u;
    for (int i = threadIdx.x; i <= XBLOCKS; i += 256) m = max(m, g_xpart[i]);
    unsigned xbits = block_umax(m, &sm);

    if (threadIdx.x < 48) swp[threadIdx.x] = g_convw_pack[threadIdx.x];
    if (threadIdx.x < 16) sb[threadIdx.x]  = conv_b[threadIdx.x];
    __syncthreads();

    float s_x   = __uint_as_float(xbits) / 7.0f + 1e-8f;
    float inv_s = 1.0f / s_x;
    float sprod = s_x * g_sw_conv;

    int idx = blockIdx.x * 256 + threadIdx.x;   // always < 294912
    int pw = idx % 6;
    int t  = idx / 6;
    int ph = t % 6;
    int b  = t / 6;

    const float* xp = x + b * IN_PIX + (4 * ph) * IN_HW + 4 * pw;  // 16B aligned

    unsigned win[24];   // [row 0..5][window j 0..3]
    #pragma unroll
    for (int r = 0; r < 6; r++) {
        float4 v4 = *(const float4*)(xp + r * IN_HW);
        float2 v2 = *(const float2*)(xp + r * IN_HW + 4);
        unsigned p0 = pack4(qcode(v4.x, inv_s), qcode(v4.y, inv_s),
                            qcode(v4.z, inv_s), qcode(v4.w, inv_s));
        unsigned p1 = pack4(qcode(v2.x, inv_s), qcode(v2.y, inv_s), 0, 0);
        win[r * 4 + 0] = p0;
        win[r * 4 + 1] = __funnelshift_r(p0, p1, 8);
        win[r * 4 + 2] = __funnelshift_r(p0, p1, 16);
        win[r * 4 + 3] = __funnelshift_r(p0, p1, 24);
    }

    float* fout = g_flat + b * FLAT_DIM + (ph * 6 + pw) * 16;
    unsigned lmax = 0u;
    float ych[4];

    #pragma unroll 1   // 4 groups of 4 channels
    for (int cg = 0; cg < 4; cg++) {
        #pragma unroll
        for (int cc = 0; cc < 4; cc++) {
            int c = cg * 4 + cc;
            int w0 = swp[c * 3 + 0];
            int w1 = swp[c * 3 + 1];
            int w2 = swp[c * 3 + 2];

            int rp[24];
            #pragma unroll
            for (int r = 0; r < 6; r++) {
                // weight row selection per conv row happens at combine time;
                // rp[r][j] must use the weight row matching its position.
                // rows contribute as: out(i,j) = rp_w0(i,j)+rp_w1(i+1,j)+rp_w2(i+2,j)
                // so compute three strips instead:
                (void)0;
            }
            // strip products: s0 rows 0..3 w0, s1 rows 1..4 w1, s2 rows 2..5 w2
            int s0[16], s1[16], s2[16];
            #pragma unroll
            for (int i = 0; i < 4; i++) {
                #pragma unroll
                for (int j = 0; j < 4; j++) {
                    s0[i * 4 + j] = __dp4a((int)win[i * 4 + j],       w0, 0);
                    s1[i * 4 + j] = __dp4a((int)win[(i + 1) * 4 + j], w1, 0);
                    s2[i * 4 + j] = __dp4a((int)win[(i + 2) * 4 + j], w2, 0);
                }
            }
            int mx = s0[0] + s1[0] + s2[0];
            #pragma unroll
            for (int p = 1; p < 16; p++)
                mx = max(mx, s0[p] + s1[p] + s2[p]);

            float y = fmaxf(fmaf((float)mx, sprod, sb[c]), 0.0f);
            ych[cc] = y;
            lmax = max(lmax, __float_as_uint(y));
        }
        *(float4*)(fout + cg * 4) = make_float4(ych[0], ych[1], ych[2], ych[3]);
    }

    lmax = block_umax(lmax, &sm);
    if (threadIdx.x == 0) g_fpart[blockIdx.x] = lmax;
}

// ---------------------------------------------------------------------------
// k_fc: 2 batch rows per warp, dp4a, redux.sync epilogue.
// ---------------------------------------------------------------------------
__global__ void __launch_bounds__(256)
k_fc(const float* __restrict__ fc_b, float* __restrict__ out) {
    __shared__ int      swq[10 * FC_GROUPS];
    __shared__ float    sbias[10];
    __shared__ unsigned sm;

    unsigned m = 0u;
    for (int i = threadIdx.x; i < CONVBLOCKS; i += 256) m = max(m, g_fpart[i]);
    unsigned fbits = block_umax(m, &sm);

    for (int i = threadIdx.x; i < 10 * FC_GROUPS; i += 256)
        swq[i] = g_fcw_pack[i];
    if (threadIdx.x < 10) sbias[threadIdx.x] = fc_b[threadIdx.x];
    __syncthreads();

    float s_f   = __uint_as_float(fbits) / 7.0f + 1e-8f;
    float inv_s = 1.0f / s_f;
    float sprod = s_f * g_sw_fc;

    int warp = threadIdx.x >> 5;
    int lane = threadIdx.x & 31;
    int b0 = (blockIdx.x * 8 + warp) * 2;      // two rows: b0, b0+1

    const float4* fr0 = (const float4*)(g_flat + b0 * FLAT_DIM);
    const float4* fr1 = (const float4*)(g_flat + (b0 + 1) * FLAT_DIM);

    int acc0[10], acc1[10];
    #pragma unroll
    for (int o = 0; o < 10; o++) { acc0[o] = 0; acc1[o] = 0; }

    #pragma unroll
    for (int it = 0; it < 5; it++) {
        int g = lane + it * 32;
        if (g < FC_GROUPS) {
            float4 v0 = fr0[g];
            float4 v1 = fr1[g];
            int p0 = (int)pack4(
                __float2int_rn(fminf(v0.x * inv_s, 7.0f)),
                __float2int_rn(fminf(v0.y * inv_s, 7.0f)),
                __float2int_rn(fminf(v0.z * inv_s, 7.0f)),
                __float2int_rn(fminf(v0.w * inv_s, 7.0f)));
            int p1 = (int)pack4(
                __float2int_rn(fminf(v1.x * inv_s, 7.0f)),
                __float2int_rn(fminf(v1.y * inv_s, 7.0f)),
                __float2int_rn(fminf(v1.z * inv_s, 7.0f)),
                __float2int_rn(fminf(v1.w * inv_s, 7.0f)));
            #pragma unroll
            for (int o = 0; o < 10; o++) {
                int w = swq[o * FC_GROUPS + g];
                acc0[o] = __dp4a(p0, w, acc0[o]);
                acc1[o] = __dp4a(p1, w, acc1[o]);
            }
        }
    }

    #pragma unroll
    for (int o = 0; o < 10; o++) {
        acc0[o] = __reduce_add_sync(0xFFFFFFFFu, acc0[o]);
        acc1[o] = __reduce_add_sync(0xFFFFFFFFu, acc1[o]);
    }

    if (lane < 10)
        out[b0 * 10 + lane] = fmaf((float)acc0[lane], sprod, sbias[lane]);
    else if (lane >= 16 && lane < 26)
        out[(b0 + 1) * 10 + (lane - 16)] =
            fmaf((float)acc1[lane - 16], sprod, sbias[lane - 16]);
}

// ---------------------------------------------------------------------------
// kernel_launch — graph-capturable, default stream, 3 kernels.
// ---------------------------------------------------------------------------
extern "C" void kernel_launch(void* const* d_in, const int* in_sizes, int n_in,
                              void* d_out, int out_size) {
    const float* x      = (const float*)d_in[0];
    const float* conv_w = (const float*)d_in[1];
    const float* conv_b = (const float*)d_in[2];
    const float* fc_w   = (const float*)d_in[3];
    const float* fc_b   = (const float*)d_in[4];
    float* out = (float*)d_out;

    int n4 = (BATCH * IN_PIX) / 4;
    k_amax<<<XBLOCKS + 1, 256>>>((const float4*)x, n4, conv_w, fc_w);
    k_conv<<<CONVBLOCKS, 256>>>(x, conv_b);
    k_fc<<<FCBLOCKS, 256>>>(fc_b, out);
}

// round 4
// speedup vs baseline: 1.0428x; 1.0428x over previous
#include <cuda_runtime.h>

// ---------------------------------------------------------------------------
// Net_17188459119113 — R4
// 4-bit quant conv(1->16,3x3) + bias + relu + maxpool(4) + 4-bit quant FC.
// B=8192. Integer-code dp4a math (exact), scales applied at the end.
//
//   k_amax : blocks 0..783 scan x with 8 unrolled float4 loads (MLP=8)
//            -> g_xpart[]; block 784 quantizes+packs both weight tensors
//   k_conv : preamble reduces g_xpart; fused conv+pool via dp4a with fused
//            accumulate; flat stored in (b, j, c) layout via 4x STG.128;
//            per-block flat max -> g_fpart[]
//   k_fc   : preamble reduces g_fpart; 2 rows/warp dp4a GEMV, redux epilogue
// ---------------------------------------------------------------------------

#define BATCH     8192
#define IN_HW     28
#define IN_PIX    784
#define FLAT_DIM  576
#define FC_GROUPS 144
#define XBLOCKS   784                 // 784*256*8 == 1605632 == n4 exactly
#define XSTRIDE   (XBLOCKS * 256)     // 200704
#define CONVBLOCKS 1152               // 8192*36 / 256
#define FCBLOCKS  512                 // 8192 / 16

__device__ float        g_flat[BATCH * FLAT_DIM];     // (b, j, c) layout
__device__ unsigned int g_xpart[XBLOCKS + 1];
__device__ unsigned int g_fpart[CONVBLOCKS];
__device__ int          g_convw_pack[48];             // [c][row]: bytes [w0,w1,w2,0]
__device__ int          g_fcw_pack[10 * FC_GROUPS];   // permuted (j,c) packing
__device__ float        g_sw_conv;
__device__ float        g_sw_fc;

__device__ __forceinline__ int qcode(float v, float inv_s) {
    return __float2int_rn(fminf(fmaxf(v * inv_s, -7.0f), 7.0f));
}
__device__ __forceinline__ unsigned pack4(int a, int b, int c, int d) {
    return (unsigned)((a & 0xff) | ((b & 0xff) << 8) | ((c & 0xff) << 16) | (d << 24));
}

__device__ __forceinline__ unsigned block_umax(unsigned m, unsigned* sm) {
    if (threadIdx.x == 0) *sm = 0u;
    __syncthreads();
    m = __reduce_max_sync(0xFFFFFFFFu, m);
    if ((threadIdx.x & 31) == 0) atomicMax(sm, m);
    __syncthreads();
    return *sm;
}

// ---------------------------------------------------------------------------
// k_amax: x abs-max partials (8 unrolled loads/thread) + weight quant block
// ---------------------------------------------------------------------------
__global__ void __launch_bounds__(256)
k_amax(const float4* __restrict__ x4,
       const float* __restrict__ conv_w, const float* __restrict__ fc_w) {
    __shared__ unsigned sm;

    if (blockIdx.x == XBLOCKS) {
        // ---- weight quantization ----
        unsigned m = 0u;
        for (int i = threadIdx.x; i < 144; i += 256)
            m = max(m, __float_as_uint(fabsf(conv_w[i])));
        unsigned cw_bits = block_umax(m, &sm);
        __syncthreads();
        m = 0u;
        for (int i = threadIdx.x; i < 5760; i += 256)
            m = max(m, __float_as_uint(fabsf(fc_w[i])));
        unsigned fw_bits = block_umax(m, &sm);

        float s_cw = __uint_as_float(cw_bits) / 7.0f + 1e-8f;
        float s_fw = __uint_as_float(fw_bits) / 7.0f + 1e-8f;
        if (threadIdx.x == 0) {
            g_sw_conv = s_cw;
            g_sw_fc   = s_fw;
            g_xpart[XBLOCKS] = 0u;
        }
        float inv_cw = 1.0f / s_cw;
        float inv_fw = 1.0f / s_fw;

        for (int i = threadIdx.x; i < 48; i += 256) {
            const float* wr = conv_w + i * 3;
            g_convw_pack[i] = (int)pack4(qcode(wr[0], inv_cw),
                                         qcode(wr[1], inv_cw),
                                         qcode(wr[2], inv_cw), 0);
        }
        // fc weights permuted: group g covers new-k = 4g..4g+3 where
        // new-k = j*16 + c  and original flat index = c*36 + j
        for (int i = threadIdx.x; i < 10 * FC_GROUPS; i += 256) {
            int o = i / FC_GROUPS, g = i % FC_GROUPS;
            int b4[4];
            #pragma unroll
            for (int t = 0; t < 4; t++) {
                int nk = 4 * g + t;
                int j = nk >> 4, c = nk & 15;
                b4[t] = qcode(fc_w[o * FLAT_DIM + c * 36 + j], inv_fw);
            }
            g_fcw_pack[i] = (int)pack4(b4[0], b4[1], b4[2], b4[3]);
        }
        return;
    }

    // ---- x scan: 8 independent, fully unrolled float4 loads ----
    int base = blockIdx.x * 256 + threadIdx.x;
    unsigned m = 0u;
    #pragma unroll
    for (int k = 0; k < 8; k++) {
        float4 v = x4[base + k * XSTRIDE];
        m = max(m, __float_as_uint(fabsf(v.x)));
        m = max(m, __float_as_uint(fabsf(v.y)));
        m = max(m, __float_as_uint(fabsf(v.z)));
        m = max(m, __float_as_uint(fabsf(v.w)));
    }
    m = block_umax(m, &sm);
    if (threadIdx.x == 0) g_xpart[blockIdx.x] = m;
}

// ---------------------------------------------------------------------------
// k_conv: thread per (b, ph, pw). 48 fused-acc dp4a per channel, int maxpool,
// scale+bias+relu, 4x STG.128 in (j,c) layout, per-block flat-max partial.
// ---------------------------------------------------------------------------
__global__ void __launch_bounds__(256)
k_conv(const float* __restrict__ x, const float* __restrict__ conv_b) {
    __shared__ int      swp[48];
    __shared__ float    sb[16];
    __shared__ unsigned sm;

    unsigned m = 0u;
    for (int i = threadIdx.x; i <= XBLOCKS; i += 256) m = max(m, g_xpart[i]);
    unsigned xbits = block_umax(m, &sm);

    if (threadIdx.x < 48) swp[threadIdx.x] = g_convw_pack[threadIdx.x];
    if (threadIdx.x < 16) sb[threadIdx.x]  = conv_b[threadIdx.x];
    __syncthreads();

    float s_x   = __uint_as_float(xbits) / 7.0f + 1e-8f;
    float inv_s = 1.0f / s_x;
    float sprod = s_x * g_sw_conv;

    int idx = blockIdx.x * 256 + threadIdx.x;   // exactly covers 294912
    int pw = idx % 6;
    int t  = idx / 6;
    int ph = t % 6;
    int b  = t / 6;

    const float* xp = x + b * IN_PIX + (4 * ph) * IN_HW + 4 * pw;  // 16B aligned

    unsigned win[24];   // [row 0..5][window j 0..3]
    #pragma unroll
    for (int r = 0; r < 6; r++) {
        float4 v4 = *(const float4*)(xp + r * IN_HW);
        float2 v2 = *(const float2*)(xp + r * IN_HW + 4);
        unsigned p0 = pack4(qcode(v4.x, inv_s), qcode(v4.y, inv_s),
                            qcode(v4.z, inv_s), qcode(v4.w, inv_s));
        unsigned p1 = pack4(qcode(v2.x, inv_s), qcode(v2.y, inv_s), 0, 0);
        win[r * 4 + 0] = p0;
        win[r * 4 + 1] = __funnelshift_r(p0, p1, 8);
        win[r * 4 + 2] = __funnelshift_r(p0, p1, 16);
        win[r * 4 + 3] = __funnelshift_r(p0, p1, 24);
    }

    float* fout = g_flat + b * FLAT_DIM + (ph * 6 + pw) * 16;
    unsigned lmax = 0u;

    #pragma unroll 1   // 4 groups of 4 channels (each group -> one STG.128)
    for (int cg = 0; cg < 4; cg++) {
        float ych[4];
        #pragma unroll
        for (int cc = 0; cc < 4; cc++) {
            int c = cg * 4 + cc;
            int w0 = swp[c * 3 + 0];
            int w1 = swp[c * 3 + 1];
            int w2 = swp[c * 3 + 2];

            int mx = -(1 << 30);
            #pragma unroll
            for (int i = 0; i < 4; i++) {
                #pragma unroll
                for (int j = 0; j < 4; j++) {
                    int acc = __dp4a((int)win[i * 4 + j],       w0, 0);
                    acc     = __dp4a((int)win[(i + 1) * 4 + j], w1, acc);
                    acc     = __dp4a((int)win[(i + 2) * 4 + j], w2, acc);
                    mx = max(mx, acc);
                }
            }
            float y = fmaxf(fmaf((float)mx, sprod, sb[c]), 0.0f);
            ych[cc] = y;
            lmax = max(lmax, __float_as_uint(y));   // y >= 0: bits monotone
        }
        *(float4*)(fout + cg * 4) = make_float4(ych[0], ych[1], ych[2], ych[3]);
    }

    lmax = block_umax(lmax, &sm);
    if (threadIdx.x == 0) g_fpart[blockIdx.x] = lmax;
}

// ---------------------------------------------------------------------------
// k_fc: 2 batch rows per warp, dp4a on packed codes, redux.sync epilogue.
// ---------------------------------------------------------------------------
__global__ void __launch_bounds__(256)
k_fc(const float* __restrict__ fc_b, float* __restrict__ out) {
    __shared__ int      swq[10 * FC_GROUPS];
    __shared__ float    sbias[10];
    __shared__ unsigned sm;

    unsigned m = 0u;
    for (int i = threadIdx.x; i < CONVBLOCKS; i += 256) m = max(m, g_fpart[i]);
    unsigned fbits = block_umax(m, &sm);

    for (int i = threadIdx.x; i < 10 * FC_GROUPS; i += 256)
        swq[i] = g_fcw_pack[i];
    if (threadIdx.x < 10) sbias[threadIdx.x] = fc_b[threadIdx.x];
    __syncthreads();

    float s_f   = __uint_as_float(fbits) / 7.0f + 1e-8f;
    float inv_s = 1.0f / s_f;
    float sprod = s_f * g_sw_fc;

    int warp = threadIdx.x >> 5;
    int lane = threadIdx.x & 31;
    int b0 = (blockIdx.x * 8 + warp) * 2;

    const float4* fr0 = (const float4*)(g_flat + b0 * FLAT_DIM);
    const float4* fr1 = (const float4*)(g_flat + (b0 + 1) * FLAT_DIM);

    int acc0[10], acc1[10];
    #pragma unroll
    for (int o = 0; o < 10; o++) { acc0[o] = 0; acc1[o] = 0; }

    #pragma unroll
    for (int it = 0; it < 5; it++) {
        int g = lane + it * 32;
        if (g < FC_GROUPS) {
            float4 v0 = fr0[g];
            float4 v1 = fr1[g];
            int p0 = (int)pack4(
                __float2int_rn(fminf(v0.x * inv_s, 7.0f)),
                __float2int_rn(fminf(v0.y * inv_s, 7.0f)),
                __float2int_rn(fminf(v0.z * inv_s, 7.0f)),
                __float2int_rn(fminf(v0.w * inv_s, 7.0f)));
            int p1 = (int)pack4(
                __float2int_rn(fminf(v1.x * inv_s, 7.0f)),
                __float2int_rn(fminf(v1.y * inv_s, 7.0f)),
                __float2int_rn(fminf(v1.z * inv_s, 7.0f)),
                __float2int_rn(fminf(v1.w * inv_s, 7.0f)));
            #pragma unroll
            for (int o = 0; o < 10; o++) {
                int w = swq[o * FC_GROUPS + g];
                acc0[o] = __dp4a(p0, w, acc0[o]);
                acc1[o] = __dp4a(p1, w, acc1[o]);
            }
        }
    }

    #pragma unroll
    for (int o = 0; o < 10; o++) {
        acc0[o] = __reduce_add_sync(0xFFFFFFFFu, acc0[o]);
        acc1[o] = __reduce_add_sync(0xFFFFFFFFu, acc1[o]);
    }

    if (lane < 10)
        out[b0 * 10 + lane] = fmaf((float)acc0[lane], sprod, sbias[lane]);
    else if (lane >= 16 && lane < 26)
        out[(b0 + 1) * 10 + (lane - 16)] =
            fmaf((float)acc1[lane - 16], sprod, sbias[lane - 16]);
}

// ---------------------------------------------------------------------------
// kernel_launch — graph-capturable, default stream, 3 kernels.
// ---------------------------------------------------------------------------
extern "C" void kernel_launch(void* const* d_in, const int* in_sizes, int n_in,
                              void* d_out, int out_size) {
    const float* x      = (const float*)d_in[0];
    const float* conv_w = (const float*)d_in[1];
    const float* conv_b = (const float*)d_in[2];
    const float* fc_w   = (const float*)d_in[3];
    const float* fc_b   = (const float*)d_in[4];
    float* out = (float*)d_out;

    k_amax<<<XBLOCKS + 1, 256>>>((const float4*)x, conv_w, fc_w);
    k_conv<<<CONVBLOCKS, 256>>>(x, conv_b);
    k_fc<<<FCBLOCKS, 256>>>(fc_b, out);
}